// round 13
// baseline (speedup 1.0000x reference)
#include <cuda_runtime.h>

// out[b, 0, h, w] = 0.5f * (x[b,0,h,w] + x[b,1,h,w] + x[b,2,h,w])
// Exact algebraic collapse of the diagonal Haar decompose + reconstruct:
//   recon(0::2,1::2) = 0.5*(up_low+up_det) = 0.5*sum_c x01
//   recon(1::2,0::2) = 0.5*(up_low-up_det) = 0.5*sum_c x10
//   recon(0::2,0::2) = 0.5*(dn_low+dn_det) = 0.5*sum_c x00
//   recon(1::2,1::2) = 0.5*(dn_low-dn_det) = 0.5*sum_c x11
// i.e. every output pixel = 0.5 * channel-sum at the same spatial location.
//
// FINAL (12 rounds). HBM roofline: 268.4 MB irreducible traffic at
// 7.3 TB/s effective (91-93% of 8 TB/s spec); remaining gap is read/write
// bus turnaround, not kernel-addressable.
// Thread-population axis (the one causally-confirmed lever) is monotone:
//   303K thr (R8 persistent)  39.20 us   DRAM 78.5%
//   1M   thr (R4 MLP=12)      38.21 us   DRAM 79.2%
//   2M   thr (R3/R5/R7/R9-11) 36.19-37.47 us   DRAM 80-82.7%
//   4M   thr (R1, R12=this)   36.77-36.83 us   DRAM 84.1-84.5%  <- best
// 4M threads (16384x256), one float4 per thread, MLP=3, 21 regs, occ 84.6%.
// Every warp LDG.128/STG is a contiguous 512B access; streaming stores.
// Flat axes: MLP depth, 128/256-bit width, load cache hints, block size.

static constexpr int B = 16;
static constexpr int C = 3;
static constexpr long long HW = 1024LL * 1024LL;            // elems per plane (2^20)
static constexpr long long OUT_ELEMS = (long long)B * HW;   // 16,777,216
static constexpr long long OUT_VECS = OUT_ELEMS / 4;        // 4,194,304 float4s
static constexpr int THREADS = 256;
static constexpr int GRID = (int)(OUT_VECS / THREADS);      // 16384, exact cover

__global__ void __launch_bounds__(THREADS) haar_chansum_kernel(
    const float* __restrict__ x, float* __restrict__ out) {
    long long v = (long long)blockIdx.x * THREADS + threadIdx.x;
    long long e = v * 4;                   // element index (float4-aligned)
    long long b = e >> 20;                 // batch (HW = 2^20)
    long long p = e & (HW - 1);            // pixel within plane
    const float* base = x + (b * C) * HW + p;

    // 3 independent, fully-coalesced LDG.128 (each warp access = 512B contiguous)
    float4 a0 = *reinterpret_cast<const float4*>(base);
    float4 a1 = *reinterpret_cast<const float4*>(base + HW);
    float4 a2 = *reinterpret_cast<const float4*>(base + 2LL * HW);

    float4 r;
    r.x = 0.5f * (a0.x + a1.x + a2.x);
    r.y = 0.5f * (a0.y + a1.y + a2.y);
    r.z = 0.5f * (a0.z + a1.z + a2.z);
    r.w = 0.5f * (a0.w + a1.w + a2.w);

    __stcs(reinterpret_cast<float4*>(out + e), r);
}

extern "C" void kernel_launch(void* const* d_in, const int* in_sizes, int n_in,
                              void* d_out, int out_size) {
    const float* x = (const float*)d_in[0];
    float* out = (float*)d_out;
    haar_chansum_kernel<<<GRID, THREADS>>>(x, out);
}

// round 14
// speedup vs baseline: 1.0077x; 1.0077x over previous
#include <cuda_runtime.h>

// out[b, 0, h, w] = 0.5f * (x[b,0,h,w] + x[b,1,h,w] + x[b,2,h,w])
// Exact algebraic collapse of the diagonal Haar decompose + reconstruct:
//   recon(0::2,1::2) = 0.5*(up_low+up_det) = 0.5*sum_c x01
//   recon(1::2,0::2) = 0.5*(up_low-up_det) = 0.5*sum_c x10
//   recon(0::2,0::2) = 0.5*(dn_low+dn_det) = 0.5*sum_c x00
//   recon(1::2,1::2) = 0.5*(dn_low-dn_det) = 0.5*sum_c x11
// i.e. every output pixel = 0.5 * channel-sum at the same spatial location.
//
// FINAL (13 rounds). HBM roofline: 268.4 MB irreducible traffic at
// 7.3 TB/s effective (91-93% of 8 TB/s spec); remaining gap is read/write
// bus turnaround, not kernel-addressable.
// Thread-population axis (the one causally-confirmed lever) is monotone:
//   303K thr (R8 persistent)   39.20 us   DRAM 78.5%
//   1M   thr (R4 MLP=12)       38.21 us   DRAM 79.2%
//   2M   thr (R3/R5/R7/R9-11)  36.19-37.47 us   DRAM 80-82.7%
//   4M   thr (R1/R12/R13=this) 36.77-37.02 us   DRAM 83.8-84.5%  <- best
// 4M threads (16384x256), one float4 per thread, MLP=3, 21 regs, occ ~82-85%.
// Every warp LDG.128/STG is a contiguous 512B access; streaming stores.
// Flat axes: MLP depth, 128/256-bit width, load cache hints, block size.

static constexpr int B = 16;
static constexpr int C = 3;
static constexpr long long HW = 1024LL * 1024LL;            // elems per plane (2^20)
static constexpr long long OUT_ELEMS = (long long)B * HW;   // 16,777,216
static constexpr long long OUT_VECS = OUT_ELEMS / 4;        // 4,194,304 float4s
static constexpr int THREADS = 256;
static constexpr int GRID = (int)(OUT_VECS / THREADS);      // 16384, exact cover

__global__ void __launch_bounds__(THREADS) haar_chansum_kernel(
    const float* __restrict__ x, float* __restrict__ out) {
    long long v = (long long)blockIdx.x * THREADS + threadIdx.x;
    long long e = v * 4;                   // element index (float4-aligned)
    long long b = e >> 20;                 // batch (HW = 2^20)
    long long p = e & (HW - 1);            // pixel within plane
    const float* base = x + (b * C) * HW + p;

    // 3 independent, fully-coalesced LDG.128 (each warp access = 512B contiguous)
    float4 a0 = *reinterpret_cast<const float4*>(base);
    float4 a1 = *reinterpret_cast<const float4*>(base + HW);
    float4 a2 = *reinterpret_cast<const float4*>(base + 2LL * HW);

    float4 r;
    r.x = 0.5f * (a0.x + a1.x + a2.x);
    r.y = 0.5f * (a0.y + a1.y + a2.y);
    r.z = 0.5f * (a0.z + a1.z + a2.z);
    r.w = 0.5f * (a0.w + a1.w + a2.w);

    __stcs(reinterpret_cast<float4*>(out + e), r);
}

extern "C" void kernel_launch(void* const* d_in, const int* in_sizes, int n_in,
                              void* d_out, int out_size) {
    const float* x = (const float*)d_in[0];
    float* out = (float*)d_out;
    haar_chansum_kernel<<<GRID, THREADS>>>(x, out);
}

// round 15
// speedup vs baseline: 1.0147x; 1.0069x over previous
#include <cuda_runtime.h>

// out[b, 0, h, w] = 0.5f * (x[b,0,h,w] + x[b,1,h,w] + x[b,2,h,w])
// Exact algebraic collapse of the diagonal Haar decompose + reconstruct:
//   recon(0::2,1::2) = 0.5*(up_low+up_det) = 0.5*sum_c x01
//   recon(1::2,0::2) = 0.5*(up_low-up_det) = 0.5*sum_c x10
//   recon(0::2,0::2) = 0.5*(dn_low+dn_det) = 0.5*sum_c x00
//   recon(1::2,1::2) = 0.5*(dn_low-dn_det) = 0.5*sum_c x11
// i.e. every output pixel = 0.5 * channel-sum at the same spatial location.
//
// FINAL (14 rounds). HBM roofline: 268.4 MB irreducible traffic at
// 7.3 TB/s effective (91-93% of 8 TB/s spec); remaining gap is read/write
// bus turnaround, not kernel-addressable.
// Thread-population axis (the one causally-confirmed lever) is monotone:
//   303K thr (R8 persistent)      39.20 us   DRAM 78.5%
//   1M   thr (R4 MLP=12)          38.21 us   DRAM 79.2%
//   2M   thr (R3/R5/R7/R9-11)     36.19-37.47 us   DRAM 80-82.7%
//   4M   thr (R1/R12/R13/R14)     36.77-37.02 us   DRAM 83.8-84.5%  <- best
// 4M threads (16384x256), one float4 per thread, MLP=3, 21 regs, occ ~82-85%.
// Every warp LDG.128/STG is a contiguous 512B access; streaming stores.
// Flat axes: MLP depth, 128/256-bit width, load cache hints, block size.

static constexpr int B = 16;
static constexpr int C = 3;
static constexpr long long HW = 1024LL * 1024LL;            // elems per plane (2^20)
static constexpr long long OUT_ELEMS = (long long)B * HW;   // 16,777,216
static constexpr long long OUT_VECS = OUT_ELEMS / 4;        // 4,194,304 float4s
static constexpr int THREADS = 256;
static constexpr int GRID = (int)(OUT_VECS / THREADS);      // 16384, exact cover

__global__ void __launch_bounds__(THREADS) haar_chansum_kernel(
    const float* __restrict__ x, float* __restrict__ out) {
    long long v = (long long)blockIdx.x * THREADS + threadIdx.x;
    long long e = v * 4;                   // element index (float4-aligned)
    long long b = e >> 20;                 // batch (HW = 2^20)
    long long p = e & (HW - 1);            // pixel within plane
    const float* base = x + (b * C) * HW + p;

    // 3 independent, fully-coalesced LDG.128 (each warp access = 512B contiguous)
    float4 a0 = *reinterpret_cast<const float4*>(base);
    float4 a1 = *reinterpret_cast<const float4*>(base + HW);
    float4 a2 = *reinterpret_cast<const float4*>(base + 2LL * HW);

    float4 r;
    r.x = 0.5f * (a0.x + a1.x + a2.x);
    r.y = 0.5f * (a0.y + a1.y + a2.y);
    r.z = 0.5f * (a0.z + a1.z + a2.z);
    r.w = 0.5f * (a0.w + a1.w + a2.w);

    __stcs(reinterpret_cast<float4*>(out + e), r);
}

extern "C" void kernel_launch(void* const* d_in, const int* in_sizes, int n_in,
                              void* d_out, int out_size) {
    const float* x = (const float*)d_in[0];
    float* out = (float*)d_out;
    haar_chansum_kernel<<<GRID, THREADS>>>(x, out);
}